// round 16
// baseline (speedup 1.0000x reference)
#include <cuda_runtime.h>
#include <cstdint>
#include <math.h>

#define NEURONS 4096
#define HIST    64
#define MID     128
#define BATCH   1024
#define TILE_M  128
#define NTHREADS 512

#define XS_STRIDE  68   // 68 mod 32 = 4 -> A-frag LDS conflict-free
#define W1S_STRIDE 136  // 136 mod 32 = 8 -> B-frag LDS conflict-free

__device__ __forceinline__ uint32_t f2tf32(float f) {
    uint32_t r;
    asm("cvt.rna.tf32.f32 %0, %1;" : "=r"(r) : "f"(f));
    return r;
}
__device__ __forceinline__ uint64_t pack2(float lo, float hi) {
    uint64_t r; asm("mov.b64 %0, {%1,%2};" : "=l"(r) : "f"(lo), "f"(hi)); return r;
}
__device__ __forceinline__ uint64_t splat2(float f) {
    uint64_t r; asm("mov.b64 %0, {%1,%1};" : "=l"(r) : "f"(f)); return r;
}

// Packed sign-free GELU (A&S 7.1.26), streamlined (poly constants pre-negated):
//   gelu(v) = 0.5*(v + |v|*(1 - u*e));  S += gelu2(v) * (0.5*w2 pair)
__device__ __forceinline__ void gelu2_acc(
    uint64_t V, uint64_t W2P,
    uint64_t C_ABS, uint64_t C_P, uint64_t C_ONE, uint64_t C_K,
    uint64_t C_C3N, uint64_t C_C2N, uint64_t C_C1N, uint64_t& S)
{
    uint64_t A, D, M, Z, T, E, U, F, G;
    asm("and.b64 %0, %1, %2;" : "=l"(A) : "l"(V), "l"(C_ABS));
    asm("fma.rn.f32x2 %0, %1, %2, %3;" : "=l"(D) : "l"(A), "l"(C_P), "l"(C_ONE));
    {
        float d0, d1, t0, t1;
        asm("mov.b64 {%0,%1}, %2;" : "=f"(d0), "=f"(d1) : "l"(D));
        asm("rcp.approx.f32 %0, %1;" : "=f"(t0) : "f"(d0));
        asm("rcp.approx.f32 %0, %1;" : "=f"(t1) : "f"(d1));
        T = pack2(t0, t1);
    }
    asm("mul.rn.f32x2 %0, %1, %2;" : "=l"(M) : "l"(V), "l"(V));
    asm("mul.rn.f32x2 %0, %1, %2;" : "=l"(Z) : "l"(M), "l"(C_K));
    {
        float z0, z1, e0, e1;
        asm("mov.b64 {%0,%1}, %2;" : "=f"(z0), "=f"(z1) : "l"(Z));
        asm("ex2.approx.f32 %0, %1;" : "=f"(e0) : "f"(z0));
        asm("ex2.approx.f32 %0, %1;" : "=f"(e1) : "f"(z1));
        E = pack2(e0, e1);
    }
    asm("fma.rn.f32x2 %0, %1, %2, %3;" : "=l"(U) : "l"(C_C3N), "l"(T), "l"(C_C2N));
    asm("fma.rn.f32x2 %0, %1, %2, %3;" : "=l"(U) : "l"(U),     "l"(T), "l"(C_C1N));
    asm("mul.rn.f32x2 %0, %1, %2;"     : "=l"(U) : "l"(U),     "l"(T));
    asm("fma.rn.f32x2 %0, %1, %2, %3;" : "=l"(F) : "l"(U), "l"(E), "l"(C_ONE));
    asm("fma.rn.f32x2 %0, %1, %2, %3;" : "=l"(G) : "l"(A), "l"(F), "l"(V));
    asm("fma.rn.f32x2 %0, %1, %2, %3;" : "=l"(S) : "l"(G), "l"(W2P), "l"(S));
}

extern "C" __global__ void __launch_bounds__(NTHREADS, 2)
neuron_mlp_v14(const float* __restrict__ x,
               const float* __restrict__ w1,
               const float* __restrict__ w2,
               float* __restrict__ out)
{
    extern __shared__ unsigned char smem_raw[];
    uint32_t* Xs  = (uint32_t*)smem_raw;                 // [128][68]  raw f32 (HW tf32-truncated)
    uint32_t* W1s = Xs + TILE_M * XS_STRIDE;             // [64][136]  tf32 (RNA)
    float*    W2s = (float*)(W1s + HIST * W1S_STRIDE);   // [128] prescaled 0.5*w2
    float*    red = W2s + MID;                           // [4][128]

    const int tid = threadIdx.x;
    const int n   = blockIdx.y;
    const int b0  = blockIdx.x * TILE_M;

    // ---- load X tile [128 x 64] raw f32: thread -> row tid>>2, quarter tid&3 ----
    {
        const int q   = tid & 3;
        const int row = tid >> 2;      // 0..127
        const float4* src = (const float4*)(x + (size_t)(b0 + row) * (NEURONS * HIST)
                                              + (size_t)n * HIST);
        float4* dst = (float4*)(Xs + row * XS_STRIDE);   // 272B row base -> 16B aligned
        #pragma unroll
        for (int i = 0; i < 4; ++i) {
            const int c = i * 4 + q;
            dst[c] = src[c];
        }
    }
    // ---- load W1 tile [64 x 128] (f32 -> tf32 RNA): thread -> row tid>>3, eighth tid&7 ----
    {
        const int e   = tid & 7;
        const int row = tid >> 3;      // 0..63
        const float4* src = (const float4*)(w1 + (size_t)n * (HIST * MID) + (size_t)row * MID);
        uint32_t* dst = W1s + row * W1S_STRIDE;
        #pragma unroll
        for (int i = 0; i < 4; ++i) {
            float4 v = src[i * 8 + e];
            const int c = (i * 8 + e) * 4;
            dst[c + 0] = f2tf32(v.x); dst[c + 1] = f2tf32(v.y);
            dst[c + 2] = f2tf32(v.z); dst[c + 3] = f2tf32(v.w);
        }
    }
    if (tid < MID) W2s[tid] = 0.5f * w2[(size_t)n * MID + tid];
    __syncthreads();

    const int warp   = tid >> 5;   // 0..15
    const int lane   = tid & 31;
    const int warp_m = warp & 3;   // 4 warps along M (32 rows each)
    const int warp_n = warp >> 2;  // 4 warps along N (32 cols each)
    const int r = lane >> 2;
    const int q = lane & 3;
    const int n0 = warp_n * 32;

    float acc[2][4][4];
    #pragma unroll
    for (int mt = 0; mt < 2; ++mt)
        #pragma unroll
        for (int nt = 0; nt < 4; ++nt)
            #pragma unroll
            for (int j = 0; j < 4; ++j) acc[mt][nt][j] = 0.f;

    #pragma unroll
    for (int k = 0; k < 8; ++k) {
        const int kk = k * 8;
        uint32_t a[2][4];
        #pragma unroll
        for (int mt = 0; mt < 2; ++mt) {
            const int m0 = warp_m * 32 + mt * 16;
            a[mt][0] = Xs[(m0 + r)     * XS_STRIDE + kk + q];
            a[mt][1] = Xs[(m0 + r + 8) * XS_STRIDE + kk + q];
            a[mt][2] = Xs[(m0 + r)     * XS_STRIDE + kk + q + 4];
            a[mt][3] = Xs[(m0 + r + 8) * XS_STRIDE + kk + q + 4];
        }
        uint32_t b[4][2];
        #pragma unroll
        for (int nt = 0; nt < 4; ++nt) {
            b[nt][0] = W1s[(kk + q)     * W1S_STRIDE + n0 + nt * 8 + r];
            b[nt][1] = W1s[(kk + q + 4) * W1S_STRIDE + n0 + nt * 8 + r];
        }
        #pragma unroll
        for (int mt = 0; mt < 2; ++mt)
            #pragma unroll
            for (int nt = 0; nt < 4; ++nt) {
                asm volatile(
                    "mma.sync.aligned.m16n8k8.row.col.f32.tf32.tf32.f32 "
                    "{%0,%1,%2,%3}, {%4,%5,%6,%7}, {%8,%9}, {%0,%1,%2,%3};"
                    : "+f"(acc[mt][nt][0]), "+f"(acc[mt][nt][1]),
                      "+f"(acc[mt][nt][2]), "+f"(acc[mt][nt][3])
                    : "r"(a[mt][0]), "r"(a[mt][1]), "r"(a[mt][2]), "r"(a[mt][3]),
                      "r"(b[nt][0]), "r"(b[nt][1]));
            }
    }

    // ---- epilogue: packed streamlined GELU, fold 0.5*w2, reduce over MID ----
    {
        const uint64_t C_ABS = 0x7FFFFFFF7FFFFFFFull;
        const uint64_t C_P   = splat2(0.3326728f);       // 0.47047/sqrt(2)
        const uint64_t C_ONE = splat2(1.0f);
        const uint64_t C_K   = splat2(-0.72134752f);     // -0.5*log2(e)
        const uint64_t C_C3N = splat2(-0.7478556f);
        const uint64_t C_C2N = splat2( 0.0958798f);
        const uint64_t C_C1N = splat2(-0.3480242f);

        uint64_t S[2][2];
        S[0][0] = splat2(0.f); S[0][1] = S[0][0];
        S[1][0] = S[0][0];     S[1][1] = S[0][0];

        #pragma unroll
        for (int nt = 0; nt < 4; ++nt) {
            const int col0 = n0 + nt * 8 + 2 * q;        // even -> 8B aligned
            const float2 wp = *(const float2*)(W2s + col0);
            const uint64_t W2P = pack2(wp.x, wp.y);
            #pragma unroll
            for (int mt = 0; mt < 2; ++mt) {
                gelu2_acc(pack2(acc[mt][nt][0], acc[mt][nt][1]), W2P,
                          C_ABS, C_P, C_ONE, C_K, C_C3N, C_C2N, C_C1N, S[mt][0]);
                gelu2_acc(pack2(acc[mt][nt][2], acc[mt][nt][3]), W2P,
                          C_ABS, C_P, C_ONE, C_K, C_C3N, C_C2N, C_C1N, S[mt][1]);
            }
        }

        #pragma unroll
        for (int mt = 0; mt < 2; ++mt) {
            float a0, a1, b0f, b1f;
            asm("mov.b64 {%0,%1}, %2;" : "=f"(a0), "=f"(a1) : "l"(S[mt][0]));
            asm("mov.b64 {%0,%1}, %2;" : "=f"(b0f), "=f"(b1f) : "l"(S[mt][1]));
            float s0 = a0 + a1;
            float s1 = b0f + b1f;
            s0 += __shfl_xor_sync(0xffffffffu, s0, 1);
            s0 += __shfl_xor_sync(0xffffffffu, s0, 2);
            s1 += __shfl_xor_sync(0xffffffffu, s1, 1);
            s1 += __shfl_xor_sync(0xffffffffu, s1, 2);
            if (q == 0) {
                const int row0 = warp_m * 32 + mt * 16 + r;
                red[warp_n * TILE_M + row0]     = s0;
                red[warp_n * TILE_M + row0 + 8] = s1;
            }
        }
    }
    __syncthreads();
    if (tid < TILE_M) {
        out[(size_t)(b0 + tid) * NEURONS + n] =
            (red[tid] + red[TILE_M + tid]) + (red[2 * TILE_M + tid] + red[3 * TILE_M + tid]);
    }
}

extern "C" void kernel_launch(void* const* d_in, const int* in_sizes, int n_in,
                              void* d_out, int out_size) {
    const float* x  = (const float*)d_in[0];
    const float* w1 = (const float*)d_in[1];
    const float* w2 = (const float*)d_in[2];
    float* out = (float*)d_out;

    const size_t smem = (size_t)(TILE_M * XS_STRIDE + HIST * W1S_STRIDE) * 4
                      + (size_t)(MID + 4 * TILE_M) * 4;   // 72192 B
    cudaFuncSetAttribute(neuron_mlp_v14,
                         cudaFuncAttributeMaxDynamicSharedMemorySize, (int)smem);

    dim3 grid(BATCH / TILE_M, NEURONS);
    neuron_mlp_v14<<<grid, NTHREADS, smem>>>(x, w1, w2, out);
}

// round 17
// speedup vs baseline: 1.0826x; 1.0826x over previous
#include <cuda_runtime.h>
#include <cstdint>
#include <math.h>

#define NEURONS 4096
#define HIST    64
#define MID     128
#define BATCH   1024
#define TILE_M  128
#define TPC     2                      // batch tiles per CTA

#define XS_STRIDE  68   // 68 mod 32 = 4 -> A-frag LDS conflict-free
#define W1S_STRIDE 136  // 136 mod 32 = 8 -> B-frag LDS conflict-free

__device__ __forceinline__ uint32_t smem_u32(const void* p) {
    uint32_t a;
    asm("{ .reg .u64 t; cvta.to.shared.u64 t, %1; cvt.u32.u64 %0, t; }" : "=r"(a) : "l"(p));
    return a;
}
__device__ __forceinline__ uint32_t f2tf32(float f) {
    uint32_t r;
    asm("cvt.rna.tf32.f32 %0, %1;" : "=r"(r) : "f"(f));
    return r;
}
__device__ __forceinline__ void cp_async16(uint32_t smem_addr, const void* gptr) {
    asm volatile("cp.async.cg.shared.global [%0], [%1], 16;"
                 :: "r"(smem_addr), "l"(gptr) : "memory");
}
__device__ __forceinline__ void cp_commit() {
    asm volatile("cp.async.commit_group;" ::: "memory");
}
template<int N> __device__ __forceinline__ void cp_wait() {
    asm volatile("cp.async.wait_group %0;" :: "n"(N) : "memory");
}
__device__ __forceinline__ uint64_t pack2(float lo, float hi) {
    uint64_t r; asm("mov.b64 %0, {%1,%2};" : "=l"(r) : "f"(lo), "f"(hi)); return r;
}
__device__ __forceinline__ uint64_t splat2(float f) {
    uint64_t r; asm("mov.b64 %0, {%1,%1};" : "=l"(r) : "f"(f)); return r;
}

// Packed sign-free GELU (A&S 7.1.26), streamlined (poly constants pre-negated):
//   gelu(v) = 0.5*(v + |v|*(1 - u*e));  S += gelu2(v) * (0.5*w2 pair)
__device__ __forceinline__ void gelu2_acc(
    uint64_t V, uint64_t W2P,
    uint64_t C_ABS, uint64_t C_P, uint64_t C_ONE, uint64_t C_K,
    uint64_t C_C3N, uint64_t C_C2N, uint64_t C_C1N, uint64_t& S)
{
    uint64_t A, D, M, Z, T, E, U, F, G;
    asm("and.b64 %0, %1, %2;" : "=l"(A) : "l"(V), "l"(C_ABS));
    asm("fma.rn.f32x2 %0, %1, %2, %3;" : "=l"(D) : "l"(A), "l"(C_P), "l"(C_ONE));
    {
        float d0, d1, t0, t1;
        asm("mov.b64 {%0,%1}, %2;" : "=f"(d0), "=f"(d1) : "l"(D));
        asm("rcp.approx.f32 %0, %1;" : "=f"(t0) : "f"(d0));
        asm("rcp.approx.f32 %0, %1;" : "=f"(t1) : "f"(d1));
        T = pack2(t0, t1);
    }
    asm("mul.rn.f32x2 %0, %1, %2;" : "=l"(M) : "l"(V), "l"(V));
    asm("mul.rn.f32x2 %0, %1, %2;" : "=l"(Z) : "l"(M), "l"(C_K));
    {
        float z0, z1, e0, e1;
        asm("mov.b64 {%0,%1}, %2;" : "=f"(z0), "=f"(z1) : "l"(Z));
        asm("ex2.approx.f32 %0, %1;" : "=f"(e0) : "f"(z0));
        asm("ex2.approx.f32 %0, %1;" : "=f"(e1) : "f"(z1));
        E = pack2(e0, e1);
    }
    asm("fma.rn.f32x2 %0, %1, %2, %3;" : "=l"(U) : "l"(C_C3N), "l"(T), "l"(C_C2N));
    asm("fma.rn.f32x2 %0, %1, %2, %3;" : "=l"(U) : "l"(U),     "l"(T), "l"(C_C1N));
    asm("mul.rn.f32x2 %0, %1, %2;"     : "=l"(U) : "l"(U),     "l"(T));
    asm("fma.rn.f32x2 %0, %1, %2, %3;" : "=l"(F) : "l"(U), "l"(E), "l"(C_ONE));
    asm("fma.rn.f32x2 %0, %1, %2, %3;" : "=l"(G) : "l"(A), "l"(F), "l"(V));
    asm("fma.rn.f32x2 %0, %1, %2, %3;" : "=l"(S) : "l"(G), "l"(W2P), "l"(S));
}

extern "C" __global__ void __launch_bounds__(256, 3)
neuron_mlp_v17(const float* __restrict__ x,
               const float* __restrict__ w1,
               const float* __restrict__ w2,
               float* __restrict__ out)
{
    extern __shared__ unsigned char smem_raw[];
    const uint32_t smem_base = smem_u32(smem_raw);
    uint32_t* Xs  = (uint32_t*)smem_raw;                 // [128][68]  raw f32 (HW tf32-truncated)
    uint32_t* W1s = Xs + TILE_M * XS_STRIDE;             // [64][136]  tf32 (RNA)
    float*    W2s = (float*)(W1s + HIST * W1S_STRIDE);   // [128] prescaled 0.5*w2
    float*    red = W2s + MID;                           // [2][128]

    const int tid = threadIdx.x;
    const int n   = blockIdx.y;
    const int bb  = blockIdx.x * (TPC * TILE_M);

    // cp.async X indexing: row = tid>>1 (0..127), 8 chunks of 16B at (tid&1)*8
    const int ld_row = tid >> 1;
    const int ld_c0  = (tid & 1) * 8;
    const uint32_t xdst = smem_base + (ld_row * XS_STRIDE) * 4;

    // ---- prologue: async-fill X tile 0 (overlaps W1 staging below) ----
    {
        const float* src = x + (size_t)(bb + ld_row) * (NEURONS * HIST) + (size_t)n * HIST;
        #pragma unroll
        for (int i = 0; i < 8; ++i)
            cp_async16(xdst + (ld_c0 + i) * 16, src + (ld_c0 + i) * 4);
        cp_commit();
    }
    // ---- stage W1 [64 x 128] (f32 -> tf32 RNA), once per CTA ----
    {
        const int q   = tid & 3;
        const int row = tid >> 2;      // 0..63
        const float4* src = (const float4*)(w1 + (size_t)n * (HIST * MID) + (size_t)row * MID);
        uint32_t* dst = W1s + row * W1S_STRIDE;
        #pragma unroll
        for (int i = 0; i < 8; ++i) {
            float4 v = src[i * 4 + q];
            int c = (i * 4 + q) * 4;
            dst[c + 0] = f2tf32(v.x); dst[c + 1] = f2tf32(v.y);
            dst[c + 2] = f2tf32(v.z); dst[c + 3] = f2tf32(v.w);
        }
    }
    if (tid < MID) W2s[tid] = 0.5f * w2[(size_t)n * MID + tid];
    cp_wait<0>();
    __syncthreads();

    const int warp   = tid >> 5;
    const int lane   = tid & 31;
    const int warp_m = warp & 3;   // 4 warps along M (32 rows each)
    const int warp_n = warp >> 2;  // 2 warps along N (64 cols each)
    const int r = lane >> 2;
    const int q = lane & 3;

    const uint64_t C_ABS = 0x7FFFFFFF7FFFFFFFull;
    const uint64_t C_P   = splat2(0.3326728f);       // 0.47047/sqrt(2)
    const uint64_t C_ONE = splat2(1.0f);
    const uint64_t C_K   = splat2(-0.72134752f);     // -0.5*log2(e)
    const uint64_t C_C3N = splat2(-0.7478556f);
    const uint64_t C_C2N = splat2( 0.0958798f);
    const uint64_t C_C1N = splat2(-0.3480242f);

    #pragma unroll 1
    for (int t = 0; t < TPC; ++t) {
        const int b0 = bb + t * TILE_M;

        uint64_t S[2][2];
        S[0][0] = splat2(0.f); S[0][1] = S[0][0];
        S[1][0] = S[0][0];     S[1][1] = S[0][0];

        // ---- two passes over this warp's 64 N-cols (32 each); pass-1 GELU overlaps
        //      the next tile's async X fill ----
        #pragma unroll 1
        for (int pass = 0; pass < 2; ++pass) {
            const int n0 = warp_n * 64 + pass * 32;

            float acc[2][4][4];
            #pragma unroll
            for (int mt = 0; mt < 2; ++mt)
                #pragma unroll
                for (int nt = 0; nt < 4; ++nt)
                    #pragma unroll
                    for (int j = 0; j < 4; ++j) acc[mt][nt][j] = 0.f;

            #pragma unroll
            for (int k = 0; k < 8; ++k) {
                const int kk = k * 8;
                uint32_t a[2][4];
                #pragma unroll
                for (int mt = 0; mt < 2; ++mt) {
                    const int m0 = warp_m * 32 + mt * 16;
                    a[mt][0] = Xs[(m0 + r)     * XS_STRIDE + kk + q];
                    a[mt][1] = Xs[(m0 + r + 8) * XS_STRIDE + kk + q];
                    a[mt][2] = Xs[(m0 + r)     * XS_STRIDE + kk + q + 4];
                    a[mt][3] = Xs[(m0 + r + 8) * XS_STRIDE + kk + q + 4];
                }
                uint32_t b[4][2];
                #pragma unroll
                for (int nt = 0; nt < 4; ++nt) {
                    b[nt][0] = W1s[(kk + q)     * W1S_STRIDE + n0 + nt * 8 + r];
                    b[nt][1] = W1s[(kk + q + 4) * W1S_STRIDE + n0 + nt * 8 + r];
                }
                #pragma unroll
                for (int mt = 0; mt < 2; ++mt)
                    #pragma unroll
                    for (int nt = 0; nt < 4; ++nt) {
                        asm volatile(
                            "mma.sync.aligned.m16n8k8.row.col.f32.tf32.tf32.f32 "
                            "{%0,%1,%2,%3}, {%4,%5,%6,%7}, {%8,%9}, {%0,%1,%2,%3};"
                            : "+f"(acc[mt][nt][0]), "+f"(acc[mt][nt][1]),
                              "+f"(acc[mt][nt][2]), "+f"(acc[mt][nt][3])
                            : "r"(a[mt][0]), "r"(a[mt][1]), "r"(a[mt][2]), "r"(a[mt][3]),
                              "r"(b[nt][0]), "r"(b[nt][1]));
                    }
            }

            if (pass == 1) {
                // all A-frag reads of this tile are done -> safe to refill Xs.
                // (unconditional: also orders tile t's out-store red-reads
                //  before tile t+1's red writes)
                __syncthreads();
                if (t + 1 < TPC) {
                    const float* src = x + (size_t)(bb + (t + 1) * TILE_M + ld_row)
                                             * (NEURONS * HIST) + (size_t)n * HIST;
                    #pragma unroll
                    for (int i = 0; i < 8; ++i)
                        cp_async16(xdst + (ld_c0 + i) * 16, src + (ld_c0 + i) * 4);
                    cp_commit();
                }
            }

            // epilogue for this pass: packed streamlined GELU folded with 0.5*w2
            #pragma unroll
            for (int nt = 0; nt < 4; ++nt) {
                const int col0 = n0 + nt * 8 + 2 * q;        // even -> 8B aligned
                const float2 wp = *(const float2*)(W2s + col0);
                const uint64_t W2P = pack2(wp.x, wp.y);
                #pragma unroll
                for (int mt = 0; mt < 2; ++mt) {
                    gelu2_acc(pack2(acc[mt][nt][0], acc[mt][nt][1]), W2P,
                              C_ABS, C_P, C_ONE, C_K, C_C3N, C_C2N, C_C1N, S[mt][0]);
                    gelu2_acc(pack2(acc[mt][nt][2], acc[mt][nt][3]), W2P,
                              C_ABS, C_P, C_ONE, C_K, C_C3N, C_C2N, C_C1N, S[mt][1]);
                }
            }
        }

        // ---- reduce + store this tile ----
        #pragma unroll
        for (int mt = 0; mt < 2; ++mt) {
            float a0, a1, b0f, b1f;
            asm("mov.b64 {%0,%1}, %2;" : "=f"(a0), "=f"(a1) : "l"(S[mt][0]));
            asm("mov.b64 {%0,%1}, %2;" : "=f"(b0f), "=f"(b1f) : "l"(S[mt][1]));
            float s0 = a0 + a1;
            float s1 = b0f + b1f;
            s0 += __shfl_xor_sync(0xffffffffu, s0, 1);
            s0 += __shfl_xor_sync(0xffffffffu, s0, 2);
            s1 += __shfl_xor_sync(0xffffffffu, s1, 1);
            s1 += __shfl_xor_sync(0xffffffffu, s1, 2);
            if (q == 0) {
                const int row0 = warp_m * 32 + mt * 16 + r;
                red[warp_n * TILE_M + row0]     = s0;
                red[warp_n * TILE_M + row0 + 8] = s1;
            }
        }
        if (t + 1 < TPC) cp_wait<0>();   // next X fill done (before the barrier)
        __syncthreads();                 // red visible; X(t+1) visible to all
        if (tid < TILE_M) {
            out[(size_t)(b0 + tid) * NEURONS + n] = red[tid] + red[TILE_M + tid];
        }
    }
}

extern "C" void kernel_launch(void* const* d_in, const int* in_sizes, int n_in,
                              void* d_out, int out_size) {
    const float* x  = (const float*)d_in[0];
    const float* w1 = (const float*)d_in[1];
    const float* w2 = (const float*)d_in[2];
    float* out = (float*)d_out;

    const size_t smem = (size_t)(TILE_M * XS_STRIDE + HIST * W1S_STRIDE) * 4
                      + (size_t)(MID + 2 * TILE_M) * 4;   // 71168 B
    cudaFuncSetAttribute(neuron_mlp_v17,
                         cudaFuncAttributeMaxDynamicSharedMemorySize, (int)smem);

    dim3 grid(BATCH / (TPC * TILE_M), NEURONS);
    neuron_mlp_v17<<<grid, 256, smem>>>(x, w1, w2, out);
}